// round 14
// baseline (speedup 1.0000x reference)
#include <cuda_runtime.h>
#include <cstdint>

// ----------------------------------------------------------------------------
// GCNConv: out = (D^-1/2 A D^-1/2)(X W) + bias,  N=8192, DIN=DOUT=256, fp32
//   K1: deg = rowsum(adj)+l ; d = deg^-1/2
//   K2: ZT[n,k] = tf32_rne( d[k] * (X@W)[k,n] )     (K-major B operand)
//   K3: out[m,n] = d[m] * sum_k adj[m,k]*ZT[n,k] + bias[n]
//       mma.sync.m16n8k8 tf32, BK=32, 3-stage cp.async ring with TWO stages
//       in flight during every compute phase (wait_group 2; issue after a
//       trailing barrier into the just-freed buffer).
// ----------------------------------------------------------------------------

#define N_NODES 8192
#define FDIM    256

__device__ float g_d[N_NODES];
__device__ float g_ZT[FDIM * (size_t)N_NODES];

// ---------------- helpers ---------------------------------------------------
__device__ __forceinline__ uint32_t smem_u32(const void* p) {
    uint32_t a;
    asm("{ .reg .u64 t; cvta.to.shared.u64 t, %1; cvt.u32.u64 %0, t; }"
        : "=r"(a) : "l"(p));
    return a;
}
__device__ __forceinline__ void cp16(uint32_t dst, const void* src) {
    asm volatile("cp.async.cg.shared.global [%0], [%1], 16;"
                 :: "r"(dst), "l"(src) : "memory");
}
__device__ __forceinline__ uint32_t f2tf32(float x) {
    uint32_t r;
    asm("cvt.rna.tf32.f32 %0, %1;" : "=r"(r) : "f"(x));
    return r;
}
__device__ __forceinline__ void mma_16n8k8(float* d, const uint32_t* a,
                                           const uint32_t* b) {
    asm volatile(
        "mma.sync.aligned.m16n8k8.row.col.f32.tf32.tf32.f32 "
        "{%0,%1,%2,%3}, {%4,%5,%6,%7}, {%8,%9}, {%0,%1,%2,%3};"
        : "+f"(d[0]), "+f"(d[1]), "+f"(d[2]), "+f"(d[3])
        : "r"(a[0]), "r"(a[1]), "r"(a[2]), "r"(a[3]), "r"(b[0]), "r"(b[1]));
}

// robust scalar 'l' reader: handles int32/int64 (small) and fp32 encodings
__device__ __forceinline__ float read_l(const void* p) {
    int i = *(const int*)p;
    if (i >= 0 && i < (1 << 24)) return (float)i;
    return __int_as_float(i);
}

// ---------------- K1: degree + D^{-1/2} -------------------------------------
__global__ __launch_bounds__(256) void k_deg(const float* __restrict__ adj,
                                             const void* __restrict__ lptr) {
    int row = blockIdx.x;
    const float4* p = (const float4*)(adj + (size_t)row * N_NODES);
    float s = 0.f;
#pragma unroll
    for (int i = 0; i < 8; i++) {
        float4 v = p[threadIdx.x + i * 256];
        s += (v.x + v.y) + (v.z + v.w);
    }
#pragma unroll
    for (int o = 16; o; o >>= 1) s += __shfl_xor_sync(0xffffffffu, s, o);
    __shared__ float ws[8];
    if ((threadIdx.x & 31) == 0) ws[threadIdx.x >> 5] = s;
    __syncthreads();
    if (threadIdx.x == 0) {
        float t = 0.f;
#pragma unroll
        for (int w = 0; w < 8; w++) t += ws[w];
        float deg = t + read_l(lptr);
        g_d[row] = deg > 0.f ? rsqrtf(deg) : 0.f;
    }
}

// ---------------- K2: ZT = d ∘ (X@W), transposed + tf32-rne -----------------
__global__ __launch_bounds__(256) void k_support(const float* __restrict__ X,
                                                 const float* __restrict__ W) {
    __shared__ float Xs[64][17];
    __shared__ float Ws[16][65];
    int k0 = blockIdx.x * 64, n0 = blockIdx.y * 64;
    int t = threadIdx.x;
    int tx = t & 15, ty = t >> 4;
    float acc[4][4] = {};
    for (int c0 = 0; c0 < FDIM; c0 += 16) {
#pragma unroll
        for (int e = t; e < 1024; e += 256) {
            int r = e >> 4, c = e & 15;
            Xs[r][c] = X[(size_t)(k0 + r) * FDIM + c0 + c];
        }
#pragma unroll
        for (int e = t; e < 1024; e += 256) {
            int c = e >> 6, n = e & 63;
            Ws[c][n] = W[(size_t)(c0 + c) * FDIM + n0 + n];
        }
        __syncthreads();
#pragma unroll
        for (int c = 0; c < 16; c++) {
            float a0 = Xs[ty * 4 + 0][c], a1 = Xs[ty * 4 + 1][c];
            float a2 = Xs[ty * 4 + 2][c], a3 = Xs[ty * 4 + 3][c];
#pragma unroll
            for (int j = 0; j < 4; j++) {
                float b = Ws[c][tx * 4 + j];
                acc[0][j] += a0 * b; acc[1][j] += a1 * b;
                acc[2][j] += a2 * b; acc[3][j] += a3 * b;
            }
        }
        __syncthreads();
    }
#pragma unroll
    for (int r = 0; r < 4; r++) {
        int k = k0 + ty * 4 + r;
        float dk = g_d[k];
#pragma unroll
        for (int j = 0; j < 4; j++) {
            int n = n0 + tx * 4 + j;
            g_ZT[(size_t)n * N_NODES + k] =
                __uint_as_float(f2tf32(dk * acc[r][j]));
        }
    }
}

// ---------------- K3: mma.sync tf32 GEMM (3-stage, 2 in flight) -------------
// BM=64, BN=256, BK=32, 3-stage cp.async ring, 128 CTAs (1 wave).
// 8 warps in 2x4 grid; warp tile 32x64 (2x8 m16n8k8 tiles), 4 k-steps/iter.
// Row stride 36 floats: fragment LDS bank = (4r + t) mod 32 -> conflict-free.
#define BM     64
#define BN     256
#define BK     32
#define NIT    (N_NODES / BK)     // 256
#define STAGES 3
#define ASTR   36
#define A_ST   (BM * ASTR)        // 2304 floats
#define B_ST   (BN * ASTR)        // 9216 floats
#define SMEM_BYTES ((STAGES * (A_ST + B_ST) + FDIM) * 4)   // 139264

__device__ __forceinline__ void issue_stage(const float* __restrict__ adj,
                                            int m0, float* sA, float* sB,
                                            int tid, int it, int s) {
    int k0 = it * BK;
#pragma unroll
    for (int j = 0; j < 2; j++) {   // A: 64 rows x 32 floats
        int f = tid + j * 256, r = f >> 3, c4 = (f & 7) * 4;
        cp16(smem_u32(sA + s * A_ST + r * ASTR + c4),
             adj + (size_t)(m0 + r) * N_NODES + k0 + c4);
    }
#pragma unroll
    for (int j = 0; j < 8; j++) {   // B: 256 rows x 32 floats
        int f = tid + j * 256, r = f >> 3, c4 = (f & 7) * 4;
        cp16(smem_u32(sB + s * B_ST + r * ASTR + c4),
             g_ZT + (size_t)r * N_NODES + k0 + c4);
    }
}

__global__ __launch_bounds__(256, 1)
void k_gemm(const float* __restrict__ adj, const float* __restrict__ bias,
            float* __restrict__ out) {
    extern __shared__ float sm[];
    float* sA = sm;
    float* sB = sm + STAGES * A_ST;
    float* sBias = sB + STAGES * B_ST;

    int tid = threadIdx.x, wid = tid >> 5, lane = tid & 31;
    int grp = lane >> 2, tig = lane & 3;
    int warpm = wid >> 2, warpn = wid & 3;   // 2 x 4 warp grid
    int m0 = blockIdx.x * BM;

    if (tid < FDIM) sBias[tid] = bias[tid];

    // prologue: fill all 3 buffers (3 committed groups in flight)
    issue_stage(adj, m0, sA, sB, tid, 0, 0);
    asm volatile("cp.async.commit_group;" ::: "memory");
    issue_stage(adj, m0, sA, sB, tid, 1, 1);
    asm volatile("cp.async.commit_group;" ::: "memory");
    issue_stage(adj, m0, sA, sB, tid, 2, 2);
    asm volatile("cp.async.commit_group;" ::: "memory");

    float acc[2][8][4] = {};
    int ar0 = warpm * 32 + grp;
    int bn0 = warpn * 64 + grp;
    int s_cur = 0;

#pragma unroll 1
    for (int it = 0; it < NIT; ++it) {
        // allow 2 pending -> stage it complete; it+1, it+2 still in flight
        asm volatile("cp.async.wait_group 2;" ::: "memory");
        __syncthreads();

        const float* As = sA + s_cur * A_ST;
        const float* Bs = sB + s_cur * B_ST;
#pragma unroll
        for (int kk = 0; kk < 4; kk++) {
            int kb = kk * 8 + tig;
            uint32_t a[2][4];
#pragma unroll
            for (int mt = 0; mt < 2; mt++) {
                int r0 = ar0 + mt * 16;
                a[mt][0] = f2tf32(As[r0 * ASTR + kb]);
                a[mt][1] = f2tf32(As[(r0 + 8) * ASTR + kb]);
                a[mt][2] = f2tf32(As[r0 * ASTR + kb + 4]);
                a[mt][3] = f2tf32(As[(r0 + 8) * ASTR + kb + 4]);
            }
            uint32_t b[8][2];
#pragma unroll
            for (int nt = 0; nt < 8; nt++) {
                int n = bn0 + nt * 8;
                b[nt][0] = __float_as_uint(Bs[n * ASTR + kb]);
                b[nt][1] = __float_as_uint(Bs[n * ASTR + kb + 4]);
            }
#pragma unroll
            for (int mt = 0; mt < 2; mt++)
#pragma unroll
                for (int nt = 0; nt < 8; nt++)
                    mma_16n8k8(acc[mt][nt], a[mt], b[nt]);
        }

        // all warps done reading buffer s_cur before refilling it
        __syncthreads();
        if (it + STAGES < NIT)
            issue_stage(adj, m0, sA, sB, tid, it + STAGES, s_cur);
        asm volatile("cp.async.commit_group;" ::: "memory");

        if (++s_cur == STAGES) s_cur = 0;
    }

    // ---- epilogue: out = d[m]*acc + bias ----
#pragma unroll
    for (int mt = 0; mt < 2; mt++) {
        int r0 = m0 + warpm * 32 + mt * 16 + grp;
        float d0 = g_d[r0], d1 = g_d[r0 + 8];
        float* o0 = out + (size_t)r0 * FDIM;
        float* o1 = out + (size_t)(r0 + 8) * FDIM;
#pragma unroll
        for (int nt = 0; nt < 8; nt++) {
            int n = warpn * 64 + nt * 8 + 2 * tig;
            float2 v0, v1;
            v0.x = acc[mt][nt][0] * d0 + sBias[n];
            v0.y = acc[mt][nt][1] * d0 + sBias[n + 1];
            v1.x = acc[mt][nt][2] * d1 + sBias[n];
            v1.y = acc[mt][nt][3] * d1 + sBias[n + 1];
            *(float2*)(o0 + n) = v0;
            *(float2*)(o1 + n) = v1;
        }
    }
}

// ---------------- launch ----------------------------------------------------
extern "C" void kernel_launch(void* const* d_in, const int* in_sizes, int n_in,
                              void* d_out, int out_size) {
    const float* adj  = (const float*)d_in[0];
    const float* X    = (const float*)d_in[1];
    const float* W    = (const float*)d_in[2];
    const float* bias = (const float*)d_in[3];
    const void*  lptr = d_in[4];
    float* out = (float*)d_out;

    cudaFuncSetAttribute(k_gemm, cudaFuncAttributeMaxDynamicSharedMemorySize,
                         SMEM_BYTES);

    k_deg<<<N_NODES, 256>>>(adj, lptr);
    k_support<<<dim3(N_NODES / 64, FDIM / 64), 256>>>(X, W);
    k_gemm<<<N_NODES / BM, 256, SMEM_BYTES>>>(adj, bias, out);
}

// round 15
// speedup vs baseline: 1.0009x; 1.0009x over previous
#include <cuda_runtime.h>
#include <cstdint>

// ----------------------------------------------------------------------------
// GCNConv: out = (D^-1/2 A D^-1/2)(X W) + bias,  N=8192, DIN=DOUT=256, fp32
//   K1: deg = rowsum(adj)+l ; d = deg^-1/2
//   K2: ZT[n,k] = tf32_rne( d[k] * (X@W)[k,n] )     (K-major B operand)
//   K3: out[m,n] = d[m] * sum_k adj[m,k]*ZT[n,k] + bias[n]
//       mma.sync.m16n8k8 tf32, BK=32, 3-stage cp.async ring, ONE barrier
//       per iteration, next-stage issue moved BEFORE compute so the fetch
//       overlaps the whole compute phase (safe: 3-deep ring, target buffer
//       was consumed last iteration and the barrier proves it).
// ----------------------------------------------------------------------------

#define N_NODES 8192
#define FDIM    256

__device__ float g_d[N_NODES];
__device__ float g_ZT[FDIM * (size_t)N_NODES];

// ---------------- helpers ---------------------------------------------------
__device__ __forceinline__ uint32_t smem_u32(const void* p) {
    uint32_t a;
    asm("{ .reg .u64 t; cvta.to.shared.u64 t, %1; cvt.u32.u64 %0, t; }"
        : "=r"(a) : "l"(p));
    return a;
}
__device__ __forceinline__ void cp16(uint32_t dst, const void* src) {
    asm volatile("cp.async.cg.shared.global [%0], [%1], 16;"
                 :: "r"(dst), "l"(src) : "memory");
}
__device__ __forceinline__ uint32_t f2tf32(float x) {
    uint32_t r;
    asm("cvt.rna.tf32.f32 %0, %1;" : "=r"(r) : "f"(x));
    return r;
}
__device__ __forceinline__ void mma_16n8k8(float* d, const uint32_t* a,
                                           const uint32_t* b) {
    asm volatile(
        "mma.sync.aligned.m16n8k8.row.col.f32.tf32.tf32.f32 "
        "{%0,%1,%2,%3}, {%4,%5,%6,%7}, {%8,%9}, {%0,%1,%2,%3};"
        : "+f"(d[0]), "+f"(d[1]), "+f"(d[2]), "+f"(d[3])
        : "r"(a[0]), "r"(a[1]), "r"(a[2]), "r"(a[3]), "r"(b[0]), "r"(b[1]));
}

// robust scalar 'l' reader: handles int32/int64 (small) and fp32 encodings
__device__ __forceinline__ float read_l(const void* p) {
    int i = *(const int*)p;
    if (i >= 0 && i < (1 << 24)) return (float)i;
    return __int_as_float(i);
}

// ---------------- K1: degree + D^{-1/2} -------------------------------------
__global__ __launch_bounds__(256) void k_deg(const float* __restrict__ adj,
                                             const void* __restrict__ lptr) {
    int row = blockIdx.x;
    const float4* p = (const float4*)(adj + (size_t)row * N_NODES);
    float s = 0.f;
#pragma unroll
    for (int i = 0; i < 8; i++) {
        float4 v = p[threadIdx.x + i * 256];
        s += (v.x + v.y) + (v.z + v.w);
    }
#pragma unroll
    for (int o = 16; o; o >>= 1) s += __shfl_xor_sync(0xffffffffu, s, o);
    __shared__ float ws[8];
    if ((threadIdx.x & 31) == 0) ws[threadIdx.x >> 5] = s;
    __syncthreads();
    if (threadIdx.x == 0) {
        float t = 0.f;
#pragma unroll
        for (int w = 0; w < 8; w++) t += ws[w];
        float deg = t + read_l(lptr);
        g_d[row] = deg > 0.f ? rsqrtf(deg) : 0.f;
    }
}

// ---------------- K2: ZT = d ∘ (X@W), transposed + tf32-rne -----------------
__global__ __launch_bounds__(256) void k_support(const float* __restrict__ X,
                                                 const float* __restrict__ W) {
    __shared__ float Xs[64][17];
    __shared__ float Ws[16][65];
    int k0 = blockIdx.x * 64, n0 = blockIdx.y * 64;
    int t = threadIdx.x;
    int tx = t & 15, ty = t >> 4;
    float acc[4][4] = {};
    for (int c0 = 0; c0 < FDIM; c0 += 16) {
#pragma unroll
        for (int e = t; e < 1024; e += 256) {
            int r = e >> 4, c = e & 15;
            Xs[r][c] = X[(size_t)(k0 + r) * FDIM + c0 + c];
        }
#pragma unroll
        for (int e = t; e < 1024; e += 256) {
            int c = e >> 6, n = e & 63;
            Ws[c][n] = W[(size_t)(c0 + c) * FDIM + n0 + n];
        }
        __syncthreads();
#pragma unroll
        for (int c = 0; c < 16; c++) {
            float a0 = Xs[ty * 4 + 0][c], a1 = Xs[ty * 4 + 1][c];
            float a2 = Xs[ty * 4 + 2][c], a3 = Xs[ty * 4 + 3][c];
#pragma unroll
            for (int j = 0; j < 4; j++) {
                float b = Ws[c][tx * 4 + j];
                acc[0][j] += a0 * b; acc[1][j] += a1 * b;
                acc[2][j] += a2 * b; acc[3][j] += a3 * b;
            }
        }
        __syncthreads();
    }
#pragma unroll
    for (int r = 0; r < 4; r++) {
        int k = k0 + ty * 4 + r;
        float dk = g_d[k];
#pragma unroll
        for (int j = 0; j < 4; j++) {
            int n = n0 + tx * 4 + j;
            g_ZT[(size_t)n * N_NODES + k] =
                __uint_as_float(f2tf32(dk * acc[r][j]));
        }
    }
}

// ---------------- K3: mma.sync tf32 GEMM (3-stage, issue-first) -------------
// BM=64, BN=256, BK=32, 3-stage cp.async ring, 128 CTAs (1 wave).
// 8 warps in 2x4 grid; warp tile 32x64 (2x8 m16n8k8 tiles), 4 k-steps/iter.
// Row stride 36 floats: fragment LDS bank = (4r + t) mod 32 -> conflict-free.
#define BM     64
#define BN     256
#define BK     32
#define NIT    (N_NODES / BK)     // 256
#define STAGES 3
#define ASTR   36
#define A_ST   (BM * ASTR)        // 2304 floats
#define B_ST   (BN * ASTR)        // 9216 floats
#define SMEM_BYTES ((STAGES * (A_ST + B_ST) + FDIM) * 4)   // 139264

__device__ __forceinline__ void issue_stage(const float* __restrict__ adj,
                                            int m0, float* sA, float* sB,
                                            int tid, int it, int s) {
    int k0 = it * BK;
#pragma unroll
    for (int j = 0; j < 2; j++) {   // A: 64 rows x 32 floats
        int f = tid + j * 256, r = f >> 3, c4 = (f & 7) * 4;
        cp16(smem_u32(sA + s * A_ST + r * ASTR + c4),
             adj + (size_t)(m0 + r) * N_NODES + k0 + c4);
    }
#pragma unroll
    for (int j = 0; j < 8; j++) {   // B: 256 rows x 32 floats
        int f = tid + j * 256, r = f >> 3, c4 = (f & 7) * 4;
        cp16(smem_u32(sB + s * B_ST + r * ASTR + c4),
             g_ZT + (size_t)r * N_NODES + k0 + c4);
    }
}

__global__ __launch_bounds__(256, 1)
void k_gemm(const float* __restrict__ adj, const float* __restrict__ bias,
            float* __restrict__ out) {
    extern __shared__ float sm[];
    float* sA = sm;
    float* sB = sm + STAGES * A_ST;
    float* sBias = sB + STAGES * B_ST;

    int tid = threadIdx.x, wid = tid >> 5, lane = tid & 31;
    int grp = lane >> 2, tig = lane & 3;
    int warpm = wid >> 2, warpn = wid & 3;   // 2 x 4 warp grid
    int m0 = blockIdx.x * BM;

    if (tid < FDIM) sBias[tid] = bias[tid];

    // prologue: stages 0 and 1 in flight
    issue_stage(adj, m0, sA, sB, tid, 0, 0);
    asm volatile("cp.async.commit_group;" ::: "memory");
    issue_stage(adj, m0, sA, sB, tid, 1, 1);
    asm volatile("cp.async.commit_group;" ::: "memory");

    float acc[2][8][4] = {};
    int ar0 = warpm * 32 + grp;
    int bn0 = warpn * 64 + grp;
    int s_cur = 0, s_nxt = STAGES - 1;

#pragma unroll 1
    for (int it = 0; it < NIT; ++it) {
        asm volatile("cp.async.wait_group %0;" :: "n"(STAGES - 2) : "memory");
        __syncthreads();

        // issue stage it+2 into the buffer consumed last iteration, BEFORE
        // compute: its fetch overlaps this whole compute phase. Safe: the
        // barrier above proves all warps finished reading that buffer.
        if (it + STAGES - 1 < NIT)
            issue_stage(adj, m0, sA, sB, tid, it + STAGES - 1, s_nxt);
        asm volatile("cp.async.commit_group;" ::: "memory");

        const float* As = sA + s_cur * A_ST;
        const float* Bs = sB + s_cur * B_ST;
#pragma unroll
        for (int kk = 0; kk < 4; kk++) {
            int kb = kk * 8 + tig;
            uint32_t a[2][4];
#pragma unroll
            for (int mt = 0; mt < 2; mt++) {
                int r0 = ar0 + mt * 16;
                a[mt][0] = f2tf32(As[r0 * ASTR + kb]);
                a[mt][1] = f2tf32(As[(r0 + 8) * ASTR + kb]);
                a[mt][2] = f2tf32(As[r0 * ASTR + kb + 4]);
                a[mt][3] = f2tf32(As[(r0 + 8) * ASTR + kb + 4]);
            }
            uint32_t b[8][2];
#pragma unroll
            for (int nt = 0; nt < 8; nt++) {
                int n = bn0 + nt * 8;
                b[nt][0] = __float_as_uint(Bs[n * ASTR + kb]);
                b[nt][1] = __float_as_uint(Bs[n * ASTR + kb + 4]);
            }
#pragma unroll
            for (int mt = 0; mt < 2; mt++)
#pragma unroll
                for (int nt = 0; nt < 8; nt++)
                    mma_16n8k8(acc[mt][nt], a[mt], b[nt]);
        }

        if (++s_cur == STAGES) s_cur = 0;
        if (++s_nxt == STAGES) s_nxt = 0;
    }

    // ---- epilogue: out = d[m]*acc + bias ----
#pragma unroll
    for (int mt = 0; mt < 2; mt++) {
        int r0 = m0 + warpm * 32 + mt * 16 + grp;
        float d0 = g_d[r0], d1 = g_d[r0 + 8];
        float* o0 = out + (size_t)r0 * FDIM;
        float* o1 = out + (size_t)(r0 + 8) * FDIM;
#pragma unroll
        for (int nt = 0; nt < 8; nt++) {
            int n = warpn * 64 + nt * 8 + 2 * tig;
            float2 v0, v1;
            v0.x = acc[mt][nt][0] * d0 + sBias[n];
            v0.y = acc[mt][nt][1] * d0 + sBias[n + 1];
            v1.x = acc[mt][nt][2] * d1 + sBias[n];
            v1.y = acc[mt][nt][3] * d1 + sBias[n + 1];
            *(float2*)(o0 + n) = v0;
            *(float2*)(o1 + n) = v1;
        }
    }
}

// ---------------- launch ----------------------------------------------------
extern "C" void kernel_launch(void* const* d_in, const int* in_sizes, int n_in,
                              void* d_out, int out_size) {
    const float* adj  = (const float*)d_in[0];
    const float* X    = (const float*)d_in[1];
    const float* W    = (const float*)d_in[2];
    const float* bias = (const float*)d_in[3];
    const void*  lptr = d_in[4];
    float* out = (float*)d_out;

    cudaFuncSetAttribute(k_gemm, cudaFuncAttributeMaxDynamicSharedMemorySize,
                         SMEM_BYTES);

    k_deg<<<N_NODES, 256>>>(adj, lptr);
    k_support<<<dim3(N_NODES / 64, FDIM / 64), 256>>>(X, W);
    k_gemm<<<N_NODES / BM, 256, SMEM_BYTES>>>(adj, bias, out);
}

// round 16
// speedup vs baseline: 1.0934x; 1.0924x over previous
#include <cuda_runtime.h>
#include <cstdint>

// ----------------------------------------------------------------------------
// GCNConv: out = (D^-1/2 A D^-1/2)(X W) + bias,  N=8192, DIN=DOUT=256, fp32
//   K1: deg = rowsum(adj)+l ; d = deg^-1/2
//   K2: ZT[n,k] = tf32_rne( d[k] * (X@W)[k,n] )     (K-major B operand)
//   K3: out[m,n] = d[m] * sum_k adj[m,k]*ZT[n,k] + bias[n]
//       mma.sync.m16n8k8 tf32, scalar-LDS fragments, BK=32, 3-stage
//       cp.async ring, issue-after-compute.  (R4 optimum: 356.9 us; all
//       11 structural variants tried across R3-R15 were neutral or worse —
//       k_gemm runs at ~88% of the legacy-HMMA MAC-rate ceiling, k_deg at
//       83% of HBM; this is the platform floor without tcgen05, which the
//       harness's compute_103 PTX lowering does not admit.)
// ----------------------------------------------------------------------------

#define N_NODES 8192
#define FDIM    256

__device__ float g_d[N_NODES];
__device__ float g_ZT[FDIM * (size_t)N_NODES];

// ---------------- helpers ---------------------------------------------------
__device__ __forceinline__ uint32_t smem_u32(const void* p) {
    uint32_t a;
    asm("{ .reg .u64 t; cvta.to.shared.u64 t, %1; cvt.u32.u64 %0, t; }"
        : "=r"(a) : "l"(p));
    return a;
}
__device__ __forceinline__ void cp16(uint32_t dst, const void* src) {
    asm volatile("cp.async.cg.shared.global [%0], [%1], 16;"
                 :: "r"(dst), "l"(src) : "memory");
}
__device__ __forceinline__ uint32_t f2tf32(float x) {
    uint32_t r;
    asm("cvt.rna.tf32.f32 %0, %1;" : "=r"(r) : "f"(x));
    return r;
}
__device__ __forceinline__ void mma_16n8k8(float* d, const uint32_t* a,
                                           const uint32_t* b) {
    asm volatile(
        "mma.sync.aligned.m16n8k8.row.col.f32.tf32.tf32.f32 "
        "{%0,%1,%2,%3}, {%4,%5,%6,%7}, {%8,%9}, {%0,%1,%2,%3};"
        : "+f"(d[0]), "+f"(d[1]), "+f"(d[2]), "+f"(d[3])
        : "r"(a[0]), "r"(a[1]), "r"(a[2]), "r"(a[3]), "r"(b[0]), "r"(b[1]));
}

// robust scalar 'l' reader: handles int32/int64 (small) and fp32 encodings
__device__ __forceinline__ float read_l(const void* p) {
    int i = *(const int*)p;
    if (i >= 0 && i < (1 << 24)) return (float)i;
    return __int_as_float(i);
}

// ---------------- K1: degree + D^{-1/2} -------------------------------------
__global__ __launch_bounds__(256) void k_deg(const float* __restrict__ adj,
                                             const void* __restrict__ lptr) {
    int row = blockIdx.x;
    const float4* p = (const float4*)(adj + (size_t)row * N_NODES);
    float s = 0.f;
#pragma unroll
    for (int i = 0; i < 8; i++) {
        float4 v = p[threadIdx.x + i * 256];
        s += (v.x + v.y) + (v.z + v.w);
    }
#pragma unroll
    for (int o = 16; o; o >>= 1) s += __shfl_xor_sync(0xffffffffu, s, o);
    __shared__ float ws[8];
    if ((threadIdx.x & 31) == 0) ws[threadIdx.x >> 5] = s;
    __syncthreads();
    if (threadIdx.x == 0) {
        float t = 0.f;
#pragma unroll
        for (int w = 0; w < 8; w++) t += ws[w];
        float deg = t + read_l(lptr);
        g_d[row] = deg > 0.f ? rsqrtf(deg) : 0.f;
    }
}

// ---------------- K2: ZT = d ∘ (X@W), transposed + tf32-rne -----------------
__global__ __launch_bounds__(256) void k_support(const float* __restrict__ X,
                                                 const float* __restrict__ W) {
    __shared__ float Xs[64][17];
    __shared__ float Ws[16][65];
    int k0 = blockIdx.x * 64, n0 = blockIdx.y * 64;
    int t = threadIdx.x;
    int tx = t & 15, ty = t >> 4;
    float acc[4][4] = {};
    for (int c0 = 0; c0 < FDIM; c0 += 16) {
#pragma unroll
        for (int e = t; e < 1024; e += 256) {
            int r = e >> 4, c = e & 15;
            Xs[r][c] = X[(size_t)(k0 + r) * FDIM + c0 + c];
        }
#pragma unroll
        for (int e = t; e < 1024; e += 256) {
            int c = e >> 6, n = e & 63;
            Ws[c][n] = W[(size_t)(c0 + c) * FDIM + n0 + n];
        }
        __syncthreads();
#pragma unroll
        for (int c = 0; c < 16; c++) {
            float a0 = Xs[ty * 4 + 0][c], a1 = Xs[ty * 4 + 1][c];
            float a2 = Xs[ty * 4 + 2][c], a3 = Xs[ty * 4 + 3][c];
#pragma unroll
            for (int j = 0; j < 4; j++) {
                float b = Ws[c][tx * 4 + j];
                acc[0][j] += a0 * b; acc[1][j] += a1 * b;
                acc[2][j] += a2 * b; acc[3][j] += a3 * b;
            }
        }
        __syncthreads();
    }
#pragma unroll
    for (int r = 0; r < 4; r++) {
        int k = k0 + ty * 4 + r;
        float dk = g_d[k];
#pragma unroll
        for (int j = 0; j < 4; j++) {
            int n = n0 + tx * 4 + j;
            g_ZT[(size_t)n * N_NODES + k] =
                __uint_as_float(f2tf32(dk * acc[r][j]));
        }
    }
}

// ---------------- K3: mma.sync tf32 GEMM (scalar-LDS frags, BK=32) ----------
// BM=64, BN=256, BK=32, 3-stage cp.async ring, 128 CTAs (1 wave).
// 8 warps in 2x4 grid; warp tile 32x64 (2x8 m16n8k8 tiles), 4 k-steps/iter.
// Row stride 36 floats (144B): fragment LDS bank = (4r+t)%32 -> conflict-free.
#define BM     64
#define BN     256
#define BK     32
#define NIT    (N_NODES / BK)     // 256
#define STAGES 3
#define ASTR   36
#define A_ST   (BM * ASTR)        // 2304 floats
#define B_ST   (BN * ASTR)        // 9216 floats
#define SMEM_FLOATS (STAGES * (A_ST + B_ST) + FDIM)
#define SMEM_BYTES  (SMEM_FLOATS * 4)   // 139264

__device__ __forceinline__ void issue_stage(const float* __restrict__ adj,
                                            int m0, float* sA, float* sB,
                                            int tid, int it) {
    int s = it;
    if (s >= STAGES) s -= STAGES;
    if (s >= STAGES) s -= STAGES;   // it passed already reduced; cheap guard
    int k0 = it * BK;
#pragma unroll
    for (int j = 0; j < 2; j++) {   // A: 64 rows x 32 floats
        int f = tid + j * 256, r = f >> 3, c4 = (f & 7) * 4;
        cp16(smem_u32(sA + s * A_ST + r * ASTR + c4),
             adj + (size_t)(m0 + r) * N_NODES + k0 + c4);
    }
#pragma unroll
    for (int j = 0; j < 8; j++) {   // B: 256 rows x 32 floats
        int f = tid + j * 256, r = f >> 3, c4 = (f & 7) * 4;
        cp16(smem_u32(sB + s * B_ST + r * ASTR + c4),
             g_ZT + (size_t)r * N_NODES + k0 + c4);
    }
}

__global__ __launch_bounds__(256, 1)
void k_gemm(const float* __restrict__ adj, const float* __restrict__ bias,
            float* __restrict__ out) {
    extern __shared__ float sm[];
    float* sA = sm;
    float* sB = sm + STAGES * A_ST;
    float* sBias = sB + STAGES * B_ST;

    int tid = threadIdx.x, wid = tid >> 5, lane = tid & 31;
    int grp = lane >> 2, tig = lane & 3;
    int warpm = wid >> 2, warpn = wid & 3;   // 2 x 4 warp grid
    int m0 = blockIdx.x * BM;

    if (tid < FDIM) sBias[tid] = bias[tid];

    // prologue: stages 0..STAGES-2
    {
        issue_stage(adj, m0, sA, sB, tid, 0);
        asm volatile("cp.async.commit_group;" ::: "memory");
        issue_stage(adj, m0, sA, sB, tid, 1);
        asm volatile("cp.async.commit_group;" ::: "memory");
    }

    float acc[2][8][4] = {};
    int s_cur = 0, s_nxt = STAGES - 1;

#pragma unroll 1
    for (int it = 0; it < NIT; ++it) {
        asm volatile("cp.async.wait_group %0;" :: "n"(STAGES - 2) : "memory");
        __syncthreads();
        const float* As = sA + s_cur * A_ST;
        const float* Bs = sB + s_cur * B_ST;
#pragma unroll
        for (int kk = 0; kk < 4; kk++) {
            int kb = kk * 8 + tig;
            uint32_t a[2][4];
#pragma unroll
            for (int mt = 0; mt < 2; mt++) {
                int r0 = warpm * 32 + mt * 16 + grp;
                a[mt][0] = f2tf32(As[r0 * ASTR + kb]);
                a[mt][1] = f2tf32(As[(r0 + 8) * ASTR + kb]);
                a[mt][2] = f2tf32(As[r0 * ASTR + kb + 4]);
                a[mt][3] = f2tf32(As[(r0 + 8) * ASTR + kb + 4]);
            }
            uint32_t b[8][2];
#pragma unroll
            for (int nt = 0; nt < 8; nt++) {
                int n = warpn * 64 + nt * 8 + grp;
                b[nt][0] = __float_as_uint(Bs[n * ASTR + kb]);
                b[nt][1] = __float_as_uint(Bs[n * ASTR + kb + 4]);
            }
#pragma unroll
            for (int mt = 0; mt < 2; mt++)
#pragma unroll
                for (int nt = 0; nt < 8; nt++)
                    mma_16n8k8(acc[mt][nt], a[mt], b[nt]);
        }
        if (it + STAGES - 1 < NIT) {
            int nit = it + STAGES - 1;
            int k0 = nit * BK;
#pragma unroll
            for (int j = 0; j < 2; j++) {
                int f = tid + j * 256, r = f >> 3, c4 = (f & 7) * 4;
                cp16(smem_u32(sA + s_nxt * A_ST + r * ASTR + c4),
                     adj + (size_t)(m0 + r) * N_NODES + k0 + c4);
            }
#pragma unroll
            for (int j = 0; j < 8; j++) {
                int f = tid + j * 256, r = f >> 3, c4 = (f & 7) * 4;
                cp16(smem_u32(sB + s_nxt * B_ST + r * ASTR + c4),
                     g_ZT + (size_t)r * N_NODES + k0 + c4);
            }
        }
        asm volatile("cp.async.commit_group;" ::: "memory");
        if (++s_cur == STAGES) s_cur = 0;
        if (++s_nxt == STAGES) s_nxt = 0;
    }

    // ---- epilogue: out = d[m]*acc + bias ----
#pragma unroll
    for (int mt = 0; mt < 2; mt++) {
        int r0 = m0 + warpm * 32 + mt * 16 + grp;
        float d0 = g_d[r0], d1 = g_d[r0 + 8];
        float* o0 = out + (size_t)r0 * FDIM;
        float* o1 = out + (size_t)(r0 + 8) * FDIM;
#pragma unroll
        for (int nt = 0; nt < 8; nt++) {
            int n = warpn * 64 + nt * 8 + 2 * tig;
            float2 v0, v1;
            v0.x = acc[mt][nt][0] * d0 + sBias[n];
            v0.y = acc[mt][nt][1] * d0 + sBias[n + 1];
            v1.x = acc[mt][nt][2] * d1 + sBias[n];
            v1.y = acc[mt][nt][3] * d1 + sBias[n + 1];
            *(float2*)(o0 + n) = v0;
            *(float2*)(o1 + n) = v1;
        }
    }
}

// ---------------- launch ----------------------------------------------------
extern "C" void kernel_launch(void* const* d_in, const int* in_sizes, int n_in,
                              void* d_out, int out_size) {
    const float* adj  = (const float*)d_in[0];
    const float* X    = (const float*)d_in[1];
    const float* W    = (const float*)d_in[2];
    const float* bias = (const float*)d_in[3];
    const void*  lptr = d_in[4];
    float* out = (float*)d_out;

    cudaFuncSetAttribute(k_gemm, cudaFuncAttributeMaxDynamicSharedMemorySize,
                         SMEM_BYTES);

    k_deg<<<N_NODES, 256>>>(adj, lptr);
    k_support<<<dim3(N_NODES / 64, FDIM / 64), 256>>>(X, W);
    k_gemm<<<N_NODES / BM, 256, SMEM_BYTES>>>(adj, bias, out);
}

// round 17
// speedup vs baseline: 1.1097x; 1.0149x over previous
#include <cuda_runtime.h>
#include <cstdint>

// ----------------------------------------------------------------------------
// GCNConv: out = (D^-1/2 A D^-1/2)(X W) + bias,  N=8192, DIN=DOUT=256, fp32
//   K1: deg = rowsum(adj)+l ; d = deg^-1/2
//   K2: ZT[n,k] = tf32_rne( d[k] * (X@W)[k,n] )     (K-major B operand)
//   K3: fine-grained split-K tf32 mma.sync GEMM: 1024 CTAs = 128 m-tiles x
//       8 K-chunks of 1024.  The R4 optimum (128 CTAs) left 20 of 148 SMs
//       idle while running at 100% of its 128-SM MAC ceiling; 1024 units
//       over 148 SMs cuts per-SM serial work from 8192 to <=7168 K-rows.
//       Deterministic: unit = f(blockIdx), raw partials to scratch.
//   K4: out = d[m] * sum_chunks part + bias
// ----------------------------------------------------------------------------

#define N_NODES 8192
#define FDIM    256

__device__ float g_d[N_NODES];
__device__ float g_ZT[FDIM * (size_t)N_NODES];
__device__ float g_part[8 * (size_t)N_NODES * FDIM];   // 64 MB partials

// ---------------- helpers ---------------------------------------------------
__device__ __forceinline__ uint32_t smem_u32(const void* p) {
    uint32_t a;
    asm("{ .reg .u64 t; cvta.to.shared.u64 t, %1; cvt.u32.u64 %0, t; }"
        : "=r"(a) : "l"(p));
    return a;
}
__device__ __forceinline__ void cp16(uint32_t dst, const void* src) {
    asm volatile("cp.async.cg.shared.global [%0], [%1], 16;"
                 :: "r"(dst), "l"(src) : "memory");
}
__device__ __forceinline__ uint32_t f2tf32(float x) {
    uint32_t r;
    asm("cvt.rna.tf32.f32 %0, %1;" : "=r"(r) : "f"(x));
    return r;
}
__device__ __forceinline__ void mma_16n8k8(float* d, const uint32_t* a,
                                           const uint32_t* b) {
    asm volatile(
        "mma.sync.aligned.m16n8k8.row.col.f32.tf32.tf32.f32 "
        "{%0,%1,%2,%3}, {%4,%5,%6,%7}, {%8,%9}, {%0,%1,%2,%3};"
        : "+f"(d[0]), "+f"(d[1]), "+f"(d[2]), "+f"(d[3])
        : "r"(a[0]), "r"(a[1]), "r"(a[2]), "r"(a[3]), "r"(b[0]), "r"(b[1]));
}

// robust scalar 'l' reader: handles int32/int64 (small) and fp32 encodings
__device__ __forceinline__ float read_l(const void* p) {
    int i = *(const int*)p;
    if (i >= 0 && i < (1 << 24)) return (float)i;
    return __int_as_float(i);
}

// ---------------- K1: degree + D^{-1/2} -------------------------------------
__global__ __launch_bounds__(256) void k_deg(const float* __restrict__ adj,
                                             const void* __restrict__ lptr) {
    int row = blockIdx.x;
    const float4* p = (const float4*)(adj + (size_t)row * N_NODES);
    float s = 0.f;
#pragma unroll
    for (int i = 0; i < 8; i++) {
        float4 v = p[threadIdx.x + i * 256];
        s += (v.x + v.y) + (v.z + v.w);
    }
#pragma unroll
    for (int o = 16; o; o >>= 1) s += __shfl_xor_sync(0xffffffffu, s, o);
    __shared__ float ws[8];
    if ((threadIdx.x & 31) == 0) ws[threadIdx.x >> 5] = s;
    __syncthreads();
    if (threadIdx.x == 0) {
        float t = 0.f;
#pragma unroll
        for (int w = 0; w < 8; w++) t += ws[w];
        float deg = t + read_l(lptr);
        g_d[row] = deg > 0.f ? rsqrtf(deg) : 0.f;
    }
}

// ---------------- K2: ZT = d ∘ (X@W), transposed + tf32-rne -----------------
__global__ __launch_bounds__(256) void k_support(const float* __restrict__ X,
                                                 const float* __restrict__ W) {
    __shared__ float Xs[64][17];
    __shared__ float Ws[16][65];
    int k0 = blockIdx.x * 64, n0 = blockIdx.y * 64;
    int t = threadIdx.x;
    int tx = t & 15, ty = t >> 4;
    float acc[4][4] = {};
    for (int c0 = 0; c0 < FDIM; c0 += 16) {
#pragma unroll
        for (int e = t; e < 1024; e += 256) {
            int r = e >> 4, c = e & 15;
            Xs[r][c] = X[(size_t)(k0 + r) * FDIM + c0 + c];
        }
#pragma unroll
        for (int e = t; e < 1024; e += 256) {
            int c = e >> 6, n = e & 63;
            Ws[c][n] = W[(size_t)(c0 + c) * FDIM + n0 + n];
        }
        __syncthreads();
#pragma unroll
        for (int c = 0; c < 16; c++) {
            float a0 = Xs[ty * 4 + 0][c], a1 = Xs[ty * 4 + 1][c];
            float a2 = Xs[ty * 4 + 2][c], a3 = Xs[ty * 4 + 3][c];
#pragma unroll
            for (int j = 0; j < 4; j++) {
                float b = Ws[c][tx * 4 + j];
                acc[0][j] += a0 * b; acc[1][j] += a1 * b;
                acc[2][j] += a2 * b; acc[3][j] += a3 * b;
            }
        }
        __syncthreads();
    }
#pragma unroll
    for (int r = 0; r < 4; r++) {
        int k = k0 + ty * 4 + r;
        float dk = g_d[k];
#pragma unroll
        for (int j = 0; j < 4; j++) {
            int n = n0 + tx * 4 + j;
            g_ZT[(size_t)n * N_NODES + k] =
                __uint_as_float(f2tf32(dk * acc[r][j]));
        }
    }
}

// ---------------- K3: fine-grained split-K tf32 GEMM ------------------------
// Unit: BM=64 x BN=256 x K-chunk=1024 (NIT=32 x BK=32), 3-stage cp.async,
// 8 warps (2x4, 32x64 warp tiles).  Grid = 128 m-tiles x 8 chunks = 1024.
// Row stride 36 floats (144B): fragment LDS bank = (4r+t)%32 -> conflict-free.
#define BM     64
#define BN     256
#define BK     32
#define KCH    1024
#define NCH    8
#define NIT    (KCH / BK)         // 32
#define STAGES 3
#define ASTR   36
#define A_ST   (BM * ASTR)        // 2304 floats
#define B_ST   (BN * ASTR)        // 9216 floats
#define SMEM_BYTES ((STAGES * (A_ST + B_ST)) * 4)   // 138240

__device__ __forceinline__ void issue_stage(const float* __restrict__ adj,
                                            int m0, int kbase, float* sA,
                                            float* sB, int tid, int it, int s) {
    int k0 = kbase + it * BK;
#pragma unroll
    for (int j = 0; j < 2; j++) {   // A: 64 rows x 32 floats
        int f = tid + j * 256, r = f >> 3, c4 = (f & 7) * 4;
        cp16(smem_u32(sA + s * A_ST + r * ASTR + c4),
             adj + (size_t)(m0 + r) * N_NODES + k0 + c4);
    }
#pragma unroll
    for (int j = 0; j < 8; j++) {   // B: 256 rows x 32 floats
        int f = tid + j * 256, r = f >> 3, c4 = (f & 7) * 4;
        cp16(smem_u32(sB + s * B_ST + r * ASTR + c4),
             g_ZT + (size_t)r * N_NODES + k0 + c4);
    }
}

__global__ __launch_bounds__(256, 1)
void k_gemm(const float* __restrict__ adj) {
    extern __shared__ float sm[];
    float* sA = sm;
    float* sB = sm + STAGES * A_ST;

    int tid = threadIdx.x, wid = tid >> 5, lane = tid & 31;
    int grp = lane >> 2, tig = lane & 3;
    int warpm = wid >> 2, warpn = wid & 3;   // 2 x 4 warp grid
    int m0 = (blockIdx.x >> 3) * BM;
    int chunk = blockIdx.x & 7;
    int kbase = chunk * KCH;

    issue_stage(adj, m0, kbase, sA, sB, tid, 0, 0);
    asm volatile("cp.async.commit_group;" ::: "memory");
    issue_stage(adj, m0, kbase, sA, sB, tid, 1, 1);
    asm volatile("cp.async.commit_group;" ::: "memory");

    float acc[2][8][4] = {};
    int ar0 = warpm * 32 + grp;
    int bn0 = warpn * 64 + grp;
    int s_cur = 0, s_nxt = STAGES - 1;

#pragma unroll 1
    for (int it = 0; it < NIT; ++it) {
        asm volatile("cp.async.wait_group %0;" :: "n"(STAGES - 2) : "memory");
        __syncthreads();
        const float* As = sA + s_cur * A_ST;
        const float* Bs = sB + s_cur * B_ST;
#pragma unroll
        for (int kk = 0; kk < 4; kk++) {
            int kb = kk * 8 + tig;
            uint32_t a[2][4];
#pragma unroll
            for (int mt = 0; mt < 2; mt++) {
                int r0 = ar0 + mt * 16;
                a[mt][0] = f2tf32(As[r0 * ASTR + kb]);
                a[mt][1] = f2tf32(As[(r0 + 8) * ASTR + kb]);
                a[mt][2] = f2tf32(As[r0 * ASTR + kb + 4]);
                a[mt][3] = f2tf32(As[(r0 + 8) * ASTR + kb + 4]);
            }
            uint32_t b[8][2];
#pragma unroll
            for (int nt = 0; nt < 8; nt++) {
                int n = bn0 + nt * 8;
                b[nt][0] = __float_as_uint(Bs[n * ASTR + kb]);
                b[nt][1] = __float_as_uint(Bs[n * ASTR + kb + 4]);
            }
#pragma unroll
            for (int mt = 0; mt < 2; mt++)
#pragma unroll
                for (int nt = 0; nt < 8; nt++)
                    mma_16n8k8(acc[mt][nt], a[mt], b[nt]);
        }
        if (it + STAGES - 1 < NIT)
            issue_stage(adj, m0, kbase, sA, sB, tid, it + STAGES - 1, s_nxt);
        asm volatile("cp.async.commit_group;" ::: "memory");
        if (++s_cur == STAGES) s_cur = 0;
        if (++s_nxt == STAGES) s_nxt = 0;
    }

    // ---- write raw partials for this chunk ----
    float* part = g_part + (size_t)chunk * N_NODES * FDIM;
#pragma unroll
    for (int mt = 0; mt < 2; mt++) {
        int r0 = m0 + warpm * 32 + mt * 16 + grp;
        float* p0 = part + (size_t)r0 * FDIM;
        float* p1 = part + (size_t)(r0 + 8) * FDIM;
#pragma unroll
        for (int nt = 0; nt < 8; nt++) {
            int n = warpn * 64 + nt * 8 + 2 * tig;
            *(float2*)(p0 + n) = make_float2(acc[mt][nt][0], acc[mt][nt][1]);
            *(float2*)(p1 + n) = make_float2(acc[mt][nt][2], acc[mt][nt][3]);
        }
    }
}

// ---------------- K4: out = d[m]*sum(partials) + bias -----------------------
__global__ __launch_bounds__(256) void k_out(const float* __restrict__ bias,
                                             float* __restrict__ out) {
    int idx = blockIdx.x * 256 + threadIdx.x;       // one float4 per thread
    int m = idx >> 6, c4 = (idx & 63) * 4;
    float dv = g_d[m];
    size_t off = (size_t)m * FDIM + c4;
    float4 s = *(const float4*)(g_part + off);
#pragma unroll
    for (int c = 1; c < NCH; c++) {
        const float4 p = *(const float4*)(g_part + (size_t)c * N_NODES * FDIM + off);
        s.x += p.x; s.y += p.y; s.z += p.z; s.w += p.w;
    }
    const float4 bv = *(const float4*)(bias + c4);
    float4 o;
    o.x = s.x * dv + bv.x;
    o.y = s.y * dv + bv.y;
    o.z = s.z * dv + bv.z;
    o.w = s.w * dv + bv.w;
    *(float4*)(out + (size_t)m * FDIM + c4) = o;
}

// ---------------- launch ----------------------------------------------------
extern "C" void kernel_launch(void* const* d_in, const int* in_sizes, int n_in,
                              void* d_out, int out_size) {
    const float* adj  = (const float*)d_in[0];
    const float* X    = (const float*)d_in[1];
    const float* W    = (const float*)d_in[2];
    const float* bias = (const float*)d_in[3];
    const void*  lptr = d_in[4];
    float* out = (float*)d_out;

    cudaFuncSetAttribute(k_gemm, cudaFuncAttributeMaxDynamicSharedMemorySize,
                         SMEM_BYTES);

    k_deg<<<N_NODES, 256>>>(adj, lptr);
    k_support<<<dim3(N_NODES / 64, FDIM / 64), 256>>>(X, W);
    k_gemm<<<(N_NODES / BM) * NCH, 256, SMEM_BYTES>>>(adj);
    k_out<<<(N_NODES * FDIM / 4) / 256, 256>>>(bias, out);
}